// round 2
// baseline (speedup 1.0000x reference)
#include <cuda_runtime.h>
#include <cstdint>
#include <cmath>

#define BSZ   32
#define SEQ   128
#define HID   512
#define NGATE 1536
#define VOC   32000
#define NTOK  4096   /* BSZ*SEQ */

// ---------------- device scratch (no allocations allowed) ----------------
__device__ int      g_tok[NTOK];
__device__ float    g_xg[(size_t)NTOK * NGATE];   // [S][B][3H], b_ih folded in
__device__ float    g_hs[(size_t)NTOK * HID];     // [S][B][H]
__device__ float    g_h[2][BSZ * HID];            // ping-pong hidden state
__device__ unsigned g_bar;                        // grid barrier counter

__device__ __forceinline__ unsigned f2tf(float x) {
    unsigned r;
    asm("cvt.rna.tf32.f32 %0, %1;" : "=r"(r) : "f"(x));
    return r;
}

// targets may be int32 (JAX x64 disabled) or int64. Detect: int64 tokens
// always have zero high words -> first 8 int64 views all in [0, VOC).
__device__ __forceinline__ bool tok_is64(const void* p) {
    const long long* q = (const long long*)p;
    bool ok = true;
#pragma unroll
    for (int i = 0; i < 8; ++i) {
        long long v = q[i];
        ok = ok && (v >= 0) && (v < VOC);
    }
    return ok;
}
__device__ __forceinline__ int tok_at(const void* p, int idx, bool is64) {
    return is64 ? (int)((const long long*)p)[idx] : ((const int*)p)[idx];
}

// ---------------- init: token gather indices, h0, barrier reset ----------
__global__ void init_kernel(const void* __restrict__ targets,
                            const int* __restrict__ init_tok,
                            const float* __restrict__ hidden) {
    const bool is64 = tok_is64(targets);
    int t = blockIdx.x * blockDim.x + threadIdx.x;
    if (t == 0) g_bar = 0u;
    if (t < NTOK) {
        int s = t >> 5, b = t & 31;
        g_tok[t] = (s == 0) ? init_tok[0]
                            : tok_at(targets, b * SEQ + (s - 1), is64);
    }
    for (int i = t; i < BSZ * HID; i += gridDim.x * blockDim.x)
        g_h[0][i] = hidden[i];
}

// ---------------- tf32 mma.sync GEMM: C[M,N] = A[M,K=512] * B[N,K]^T + bias
// MODE 0: A rows gathered via g_tok (embedding), C -> g_xg row-major [t][n]
// MODE 1: A = g_hs rows, C -> logits[b][s][v] with t = s*32+b
template <int MODE>
__global__ void __launch_bounds__(256, 2)
gemm_tf32(const float* __restrict__ A, const float* __restrict__ Bm,
          const float* __restrict__ bias, float* __restrict__ C) {
    __shared__ unsigned As[128 * 36];
    __shared__ unsigned Bs[128 * 36];

    const int tid  = threadIdx.x;
    const int n0   = blockIdx.x * 128;
    const int m0   = blockIdx.y * 128;
    const int lane = tid & 31, warp = tid >> 5;
    const int wm = warp & 1, wn = warp >> 1;       // 2 x 4 warp grid
    const int g  = lane >> 2, tg = lane & 3;

    const float* Ap = (MODE == 1) ? g_hs : A;

    const float* aptr[4];
    const float* bptr[4];
    int soff[4];
#pragma unroll
    for (int i = 0; i < 4; ++i) {
        int idx = tid + i * 256;           // 1024 float4 per 128x32 tile
        int row = idx >> 3, cv = idx & 7;
        int arow = (MODE == 0) ? g_tok[m0 + row] : (m0 + row);
        aptr[i] = Ap + (size_t)arow * HID + cv * 4;
        bptr[i] = Bm + (size_t)(n0 + row) * HID + cv * 4;
        soff[i] = row * 36 + cv * 4;
    }

    float c[4][4][4];
#pragma unroll
    for (int a = 0; a < 4; ++a)
#pragma unroll
        for (int b = 0; b < 4; ++b)
#pragma unroll
            for (int k = 0; k < 4; ++k) c[a][b][k] = 0.f;

    for (int kt = 0; kt < 16; ++kt) {
        float4 va[4], vb[4];
#pragma unroll
        for (int i = 0; i < 4; ++i) {
            va[i] = *(const float4*)(aptr[i] + kt * 32);
            vb[i] = *(const float4*)(bptr[i] + kt * 32);
        }
        __syncthreads();   // previous tile's compute done before overwrite
#pragma unroll
        for (int i = 0; i < 4; ++i) {
            As[soff[i] + 0] = f2tf(va[i].x); As[soff[i] + 1] = f2tf(va[i].y);
            As[soff[i] + 2] = f2tf(va[i].z); As[soff[i] + 3] = f2tf(va[i].w);
            Bs[soff[i] + 0] = f2tf(vb[i].x); Bs[soff[i] + 1] = f2tf(vb[i].y);
            Bs[soff[i] + 2] = f2tf(vb[i].z); Bs[soff[i] + 3] = f2tf(vb[i].w);
        }
        __syncthreads();

#pragma unroll
        for (int kk = 0; kk < 4; ++kk) {
            const int kb = kk * 8;
            unsigned afr[4][4], bfr[4][2];
#pragma unroll
            for (int mf = 0; mf < 4; ++mf) {
                int r0 = (wm * 64 + mf * 16 + g) * 36 + kb + tg;
                afr[mf][0] = As[r0];
                afr[mf][1] = As[r0 + 8 * 36];
                afr[mf][2] = As[r0 + 4];
                afr[mf][3] = As[r0 + 8 * 36 + 4];
            }
#pragma unroll
            for (int nf = 0; nf < 4; ++nf) {
                int r0 = (wn * 32 + nf * 8 + g) * 36 + kb + tg;
                bfr[nf][0] = Bs[r0];
                bfr[nf][1] = Bs[r0 + 4];
            }
#pragma unroll
            for (int mf = 0; mf < 4; ++mf)
#pragma unroll
                for (int nf = 0; nf < 4; ++nf) {
                    asm volatile(
                        "mma.sync.aligned.m16n8k8.row.col.f32.tf32.tf32.f32 "
                        "{%0,%1,%2,%3}, {%4,%5,%6,%7}, {%8,%9}, {%0,%1,%2,%3};"
                        : "+f"(c[mf][nf][0]), "+f"(c[mf][nf][1]),
                          "+f"(c[mf][nf][2]), "+f"(c[mf][nf][3])
                        : "r"(afr[mf][0]), "r"(afr[mf][1]),
                          "r"(afr[mf][2]), "r"(afr[mf][3]),
                          "r"(bfr[nf][0]), "r"(bfr[nf][1]));
                }
        }
    }

    // epilogue
    float* Cx = (MODE == 0) ? g_xg : C;
#pragma unroll
    for (int mf = 0; mf < 4; ++mf) {
#pragma unroll
        for (int nf = 0; nf < 4; ++nf) {
            int row = m0 + wm * 64 + mf * 16 + g;
            int col = n0 + wn * 32 + nf * 8 + 2 * tg;
            float b0v = bias[col], b1v = bias[col + 1];
            float2 v0 = make_float2(c[mf][nf][0] + b0v, c[mf][nf][1] + b1v);
            float2 v1 = make_float2(c[mf][nf][2] + b0v, c[mf][nf][3] + b1v);
            if (MODE == 0) {
                *(float2*)&Cx[(size_t)row * NGATE + col]       = v0;
                *(float2*)&Cx[(size_t)(row + 8) * NGATE + col] = v1;
            } else {
                int s0 = row >> 5, b0i = row & 31;
                *(float2*)&Cx[((size_t)b0i * SEQ + s0) * VOC + col] = v0;
                int r1 = row + 8;
                int s1 = r1 >> 5, b1i = r1 & 31;
                *(float2*)&Cx[((size_t)b1i * SEQ + s1) * VOC + col] = v1;
            }
        }
    }
}

// ---------------- persistent GRU scan: 128 CTAs, grid barrier per step ----
// CTA c owns hidden units j0 = 4c .. 4c+3. W_hh slice (12 rows) resident in
// SMEM for all 128 steps; h (32x512 fp32 = 64KB) reloaded per step.
__global__ void recur_kernel(const float* __restrict__ W_hh,
                             const float* __restrict__ b_hh) {
    extern __shared__ float sm[];
    float* h_sm    = sm;                  // 16384 floats
    float* w_sm    = sm + BSZ * HID;      // 12*512 floats
    float* bias_sm = w_sm + 12 * HID;     // 12 floats

    const int tid = threadIdx.x;
    const int j0  = blockIdx.x * 4;

    for (int i = tid; i < 12 * HID; i += 256) {
        int r = i >> 9, k = i & 511;
        int jl = r / 3, gg = r % 3;
        w_sm[i] = W_hh[(size_t)(gg * HID + j0 + jl) * HID + k];
    }
    if (tid < 12) {
        int jl = tid / 3, gg = tid % 3;
        bias_sm[tid] = b_hh[gg * HID + j0 + jl];
    }

    const int ks = tid & 15;          // 16-way k split, interleaved
    const int bq = (tid >> 4) & 3;    // 4 batch quads (8 b each)
    const int jl = tid >> 6;          // 4 hidden units per CTA
    const int j  = j0 + jl;
    const float* wr = w_sm + (jl * 3 + 0) * HID;
    const float* wz = w_sm + (jl * 3 + 1) * HID;
    const float* wn = w_sm + (jl * 3 + 2) * HID;
    __syncthreads();

    for (int s = 0; s < SEQ; ++s) {
        // broadcast h into smem
        {
            const float4* src = (const float4*)g_h[s & 1];
            float4* dst = (float4*)h_sm;
            for (int i = tid; i < (BSZ * HID) / 4; i += 256) dst[i] = src[i];
        }
        __syncthreads();

        float ar[8], az[8], an[8];
#pragma unroll
        for (int bi = 0; bi < 8; ++bi) { ar[bi] = az[bi] = an[bi] = 0.f; }
#pragma unroll
        for (int i = 0; i < 8; ++i) {
            int k = ks * 4 + i * 64;           // conflict-free per phase group
            float4 r4 = *(const float4*)(wr + k);
            float4 z4 = *(const float4*)(wz + k);
            float4 n4 = *(const float4*)(wn + k);
#pragma unroll
            for (int bi = 0; bi < 8; ++bi) {
                int b = bq * 8 + bi;
                float4 h4 = *(const float4*)(h_sm + b * HID + k);
                ar[bi] += h4.x * r4.x + h4.y * r4.y + h4.z * r4.z + h4.w * r4.w;
                az[bi] += h4.x * z4.x + h4.y * z4.y + h4.z * z4.z + h4.w * z4.w;
                an[bi] += h4.x * n4.x + h4.y * n4.y + h4.z * n4.z + h4.w * n4.w;
            }
        }
        // reduce across the 16 k-split lanes (lane%16 == ks)
#pragma unroll
        for (int off = 8; off > 0; off >>= 1) {
#pragma unroll
            for (int bi = 0; bi < 8; ++bi) {
                ar[bi] += __shfl_xor_sync(0xffffffffu, ar[bi], off);
                az[bi] += __shfl_xor_sync(0xffffffffu, az[bi], off);
                an[bi] += __shfl_xor_sync(0xffffffffu, an[bi], off);
            }
        }
        if (ks == 0) {
            float br = bias_sm[jl * 3 + 0];
            float bz = bias_sm[jl * 3 + 1];
            float bn = bias_sm[jl * 3 + 2];
#pragma unroll
            for (int bi = 0; bi < 8; ++bi) {
                int b = bq * 8 + bi;
                const float* xg = g_xg + (size_t)(s * BSZ + b) * NGATE;
                float rr = 1.f / (1.f + expf(-(xg[j]           + ar[bi] + br)));
                float zz = 1.f / (1.f + expf(-(xg[HID + j]     + az[bi] + bz)));
                float nn = tanhf(xg[2 * HID + j] + rr * (an[bi] + bn));
                float hold = h_sm[b * HID + j];
                float hnew = (1.f - zz) * nn + zz * hold;
                g_h[(s + 1) & 1][b * HID + j]           = hnew;
                g_hs[(size_t)(s * BSZ + b) * HID + j]   = hnew;
            }
        }
        if (s == SEQ - 1) break;

        // ---- grid barrier ----
        __threadfence();        // make this thread's writes globally visible
        __syncthreads();        // all writers in CTA have fenced
        if (tid == 0) {
            atomicAdd(&g_bar, 1u);
            unsigned target = gridDim.x * (unsigned)(s + 1);
            while (*((volatile unsigned*)&g_bar) < target) { }
            __threadfence();    // acquire side
        }
        __syncthreads();
    }
}

// ---------------- launch ----------------
extern "C" void kernel_launch(void* const* d_in, const int* in_sizes, int n_in,
                              void* d_out, int out_size) {
    const float* hidden    = (const float*)d_in[0];
    const void*  targets   = (const void*)d_in[1];
    const float* embedding = (const float*)d_in[2];
    const float* W_ih      = (const float*)d_in[3];
    const float* W_hh      = (const float*)d_in[4];
    const float* b_ih      = (const float*)d_in[5];
    const float* b_hh      = (const float*)d_in[6];
    const float* W_out     = (const float*)d_in[7];
    const float* b_out     = (const float*)d_in[8];
    const int*   init_tok  = (const int*)d_in[9];
    float*       out       = (float*)d_out;

    cudaFuncSetAttribute(recur_kernel,
                         cudaFuncAttributeMaxDynamicSharedMemorySize, 92160);

    init_kernel<<<16, 256>>>(targets, init_tok, hidden);

    // x_gates: [4096 x 1536 x 512], A gathered from embedding
    gemm_tf32<0><<<dim3(NGATE / 128, NTOK / 128), 256>>>(
        embedding, W_ih, b_ih, nullptr);

    // sequential GRU scan (persistent, 128 co-resident CTAs)
    recur_kernel<<<128, 256, 92160>>>(W_hh, b_hh);

    // logits: [4096 x 32000 x 512]
    gemm_tf32<1><<<dim3(VOC / 128, NTOK / 128), 256>>>(
        nullptr, W_out, b_out, out);
}

// round 3
// speedup vs baseline: 1.3811x; 1.3811x over previous
#include <cuda_runtime.h>
#include <cstdint>
#include <cmath>

#define BSZ   32
#define SEQ   128
#define HID   512
#define NGATE 1536
#define VOC   32000
#define NTOK  4096   /* BSZ*SEQ */

// ---------------- device scratch (no allocations allowed) ----------------
__device__ int      g_tok[NTOK];
__device__ float    g_xg[(size_t)NTOK * NGATE];   // [S][B][3H], b_ih folded in
__device__ float    g_hs[(size_t)NTOK * HID];     // [S][B][H]
__device__ float    g_h[2][BSZ * HID];            // ping-pong hidden state
__device__ unsigned g_bar;                        // arrival counter
__device__ unsigned g_flag[128 * 32];             // per-CTA release flags (128B apart)

__device__ __forceinline__ unsigned f2tf(float x) {
    unsigned r;
    asm("cvt.rna.tf32.f32 %0, %1;" : "=r"(r) : "f"(x));
    return r;
}

// targets may be int32 (JAX x64 disabled) or int64. Detect: int64 tokens
// always have zero high words -> first 8 int64 views all in [0, VOC).
__device__ __forceinline__ bool tok_is64(const void* p) {
    const long long* q = (const long long*)p;
    bool ok = true;
#pragma unroll
    for (int i = 0; i < 8; ++i) {
        long long v = q[i];
        ok = ok && (v >= 0) && (v < VOC);
    }
    return ok;
}
__device__ __forceinline__ int tok_at(const void* p, int idx, bool is64) {
    return is64 ? (int)((const long long*)p)[idx] : ((const int*)p)[idx];
}

__device__ __forceinline__ float fsigm(float x) {
    return __fdividef(1.f, 1.f + __expf(-x));
}
__device__ __forceinline__ float ftanh(float x) {
    float ax = fabsf(x);
    float e  = __expf(-2.f * ax);                 // in (0,1], overflow-safe
    float t  = __fdividef(1.f - e, 1.f + e);
    return copysignf(t, x);
}

// ---------------- init: token gather indices, h0, barrier reset ----------
__global__ void init_kernel(const void* __restrict__ targets,
                            const int* __restrict__ init_tok,
                            const float* __restrict__ hidden) {
    const bool is64 = tok_is64(targets);
    int t = blockIdx.x * blockDim.x + threadIdx.x;
    int nt = gridDim.x * blockDim.x;
    if (t == 0) g_bar = 0u;
    for (int i = t; i < 128 * 32; i += nt) g_flag[i] = 0u;
    if (t < NTOK) {
        int s = t >> 5, b = t & 31;
        g_tok[t] = (s == 0) ? init_tok[0]
                            : tok_at(targets, b * SEQ + (s - 1), is64);
    }
    for (int i = t; i < BSZ * HID; i += nt)
        g_h[0][i] = hidden[i];
}

// ---------------- tf32 mma.sync GEMM: C[M,N] = A[M,K=512] * B[N,K]^T + bias
// MODE 0: A rows gathered via g_tok (embedding), C -> g_xg row-major [t][n]
// MODE 1: A = g_hs rows, C -> logits[b][s][v] with t = s*32+b
template <int MODE>
__global__ void __launch_bounds__(256, 2)
gemm_tf32(const float* __restrict__ A, const float* __restrict__ Bm,
          const float* __restrict__ bias, float* __restrict__ C) {
    __shared__ unsigned As[128 * 36];
    __shared__ unsigned Bs[128 * 36];

    const int tid  = threadIdx.x;
    const int n0   = blockIdx.x * 128;
    const int m0   = blockIdx.y * 128;
    const int lane = tid & 31, warp = tid >> 5;
    const int wm = warp & 1, wn = warp >> 1;       // 2 x 4 warp grid
    const int g  = lane >> 2, tg = lane & 3;

    const float* Ap = (MODE == 1) ? g_hs : A;

    const float* aptr[4];
    const float* bptr[4];
    int soff[4];
#pragma unroll
    for (int i = 0; i < 4; ++i) {
        int idx = tid + i * 256;           // 1024 float4 per 128x32 tile
        int row = idx >> 3, cv = idx & 7;
        int arow = (MODE == 0) ? g_tok[m0 + row] : (m0 + row);
        aptr[i] = Ap + (size_t)arow * HID + cv * 4;
        bptr[i] = Bm + (size_t)(n0 + row) * HID + cv * 4;
        soff[i] = row * 36 + cv * 4;
    }

    float c[4][4][4];
#pragma unroll
    for (int a = 0; a < 4; ++a)
#pragma unroll
        for (int b = 0; b < 4; ++b)
#pragma unroll
            for (int k = 0; k < 4; ++k) c[a][b][k] = 0.f;

    for (int kt = 0; kt < 16; ++kt) {
        float4 va[4], vb[4];
#pragma unroll
        for (int i = 0; i < 4; ++i) {
            va[i] = *(const float4*)(aptr[i] + kt * 32);
            vb[i] = *(const float4*)(bptr[i] + kt * 32);
        }
        __syncthreads();   // previous tile's compute done before overwrite
#pragma unroll
        for (int i = 0; i < 4; ++i) {
            As[soff[i] + 0] = f2tf(va[i].x); As[soff[i] + 1] = f2tf(va[i].y);
            As[soff[i] + 2] = f2tf(va[i].z); As[soff[i] + 3] = f2tf(va[i].w);
            Bs[soff[i] + 0] = f2tf(vb[i].x); Bs[soff[i] + 1] = f2tf(vb[i].y);
            Bs[soff[i] + 2] = f2tf(vb[i].z); Bs[soff[i] + 3] = f2tf(vb[i].w);
        }
        __syncthreads();

#pragma unroll
        for (int kk = 0; kk < 4; ++kk) {
            const int kb = kk * 8;
            unsigned afr[4][4], bfr[4][2];
#pragma unroll
            for (int mf = 0; mf < 4; ++mf) {
                int r0 = (wm * 64 + mf * 16 + g) * 36 + kb + tg;
                afr[mf][0] = As[r0];
                afr[mf][1] = As[r0 + 8 * 36];
                afr[mf][2] = As[r0 + 4];
                afr[mf][3] = As[r0 + 8 * 36 + 4];
            }
#pragma unroll
            for (int nf = 0; nf < 4; ++nf) {
                int r0 = (wn * 32 + nf * 8 + g) * 36 + kb + tg;
                bfr[nf][0] = Bs[r0];
                bfr[nf][1] = Bs[r0 + 4];
            }
#pragma unroll
            for (int mf = 0; mf < 4; ++mf)
#pragma unroll
                for (int nf = 0; nf < 4; ++nf) {
                    asm volatile(
                        "mma.sync.aligned.m16n8k8.row.col.f32.tf32.tf32.f32 "
                        "{%0,%1,%2,%3}, {%4,%5,%6,%7}, {%8,%9}, {%0,%1,%2,%3};"
                        : "+f"(c[mf][nf][0]), "+f"(c[mf][nf][1]),
                          "+f"(c[mf][nf][2]), "+f"(c[mf][nf][3])
                        : "r"(afr[mf][0]), "r"(afr[mf][1]),
                          "r"(afr[mf][2]), "r"(afr[mf][3]),
                          "r"(bfr[nf][0]), "r"(bfr[nf][1]));
                }
        }
    }

    // epilogue
    float* Cx = (MODE == 0) ? g_xg : C;
#pragma unroll
    for (int mf = 0; mf < 4; ++mf) {
#pragma unroll
        for (int nf = 0; nf < 4; ++nf) {
            int row = m0 + wm * 64 + mf * 16 + g;
            int col = n0 + wn * 32 + nf * 8 + 2 * tg;
            float b0v = bias[col], b1v = bias[col + 1];
            float2 v0 = make_float2(c[mf][nf][0] + b0v, c[mf][nf][1] + b1v);
            float2 v1 = make_float2(c[mf][nf][2] + b0v, c[mf][nf][3] + b1v);
            if (MODE == 0) {
                *(float2*)&Cx[(size_t)row * NGATE + col]       = v0;
                *(float2*)&Cx[(size_t)(row + 8) * NGATE + col] = v1;
            } else {
                int s0 = row >> 5, b0i = row & 31;
                *(float2*)&Cx[((size_t)b0i * SEQ + s0) * VOC + col] = v0;
                int r1 = row + 8;
                int s1 = r1 >> 5, b1i = r1 & 31;
                *(float2*)&Cx[((size_t)b1i * SEQ + s1) * VOC + col] = v1;
            }
        }
    }
}

// ---------------- persistent GRU scan: 128 CTAs, grid barrier per step ----
// CTA c owns hidden units j0 = 4c .. 4c+3. W_hh slice (12 rows) resident in
// SMEM for all 128 steps; h (32x512 fp32 = 64KB) reloaded per step.
__global__ void recur_kernel(const float* __restrict__ W_hh,
                             const float* __restrict__ b_hh) {
    extern __shared__ float sm[];
    float* h_sm    = sm;                  // 16384 floats
    float* w_sm    = sm + BSZ * HID;      // 12*512 floats
    float* bias_sm = w_sm + 12 * HID;     // 12 floats

    const int tid = threadIdx.x;
    const int j0  = blockIdx.x * 4;

    for (int i = tid; i < 12 * HID; i += 256) {
        int r = i >> 9, k = i & 511;
        int jl = r / 3, gg = r % 3;
        w_sm[i] = W_hh[(size_t)(gg * HID + j0 + jl) * HID + k];
    }
    if (tid < 12) {
        int jl = tid / 3, gg = tid % 3;
        bias_sm[tid] = b_hh[gg * HID + j0 + jl];
    }

    const int ks = tid & 15;          // 16-way k split, interleaved
    const int bq = (tid >> 4) & 3;    // 4 batch quads (8 b each)
    const int jl = tid >> 6;          // 4 hidden units per CTA
    const int j  = j0 + jl;
    const float* wr = w_sm + (jl * 3 + 0) * HID;
    const float* wz = w_sm + (jl * 3 + 1) * HID;
    const float* wn = w_sm + (jl * 3 + 2) * HID;
    __syncthreads();

    for (int s = 0; s < SEQ; ++s) {
        // prefetch epilogue inputs (independent of h) so LDG latency hides
        // under the h broadcast + compute
        float xr[8], xz[8], xn[8];
        if (ks == 0) {
#pragma unroll
            for (int bi = 0; bi < 8; ++bi) {
                int b = bq * 8 + bi;
                const float* xg = g_xg + (size_t)(s * BSZ + b) * NGATE;
                xr[bi] = __ldg(xg + j);
                xz[bi] = __ldg(xg + HID + j);
                xn[bi] = __ldg(xg + 2 * HID + j);
            }
        }

        // broadcast h into smem
        {
            const float4* src = (const float4*)g_h[s & 1];
            float4* dst = (float4*)h_sm;
            for (int i = tid; i < (BSZ * HID) / 4; i += 256) dst[i] = src[i];
        }
        __syncthreads();

        float ar[8], az[8], an[8];
#pragma unroll
        for (int bi = 0; bi < 8; ++bi) { ar[bi] = az[bi] = an[bi] = 0.f; }
#pragma unroll
        for (int i = 0; i < 8; ++i) {
            int k = ks * 4 + i * 64;           // conflict-free per phase group
            float4 r4 = *(const float4*)(wr + k);
            float4 z4 = *(const float4*)(wz + k);
            float4 n4 = *(const float4*)(wn + k);
#pragma unroll
            for (int bi = 0; bi < 8; ++bi) {
                int b = bq * 8 + bi;
                float4 h4 = *(const float4*)(h_sm + b * HID + k);
                ar[bi] += h4.x * r4.x + h4.y * r4.y + h4.z * r4.z + h4.w * r4.w;
                az[bi] += h4.x * z4.x + h4.y * z4.y + h4.z * z4.z + h4.w * z4.w;
                an[bi] += h4.x * n4.x + h4.y * n4.y + h4.z * n4.z + h4.w * n4.w;
            }
        }
        // reduce across the 16 k-split lanes (lane%16 == ks)
#pragma unroll
        for (int off = 8; off > 0; off >>= 1) {
#pragma unroll
            for (int bi = 0; bi < 8; ++bi) {
                ar[bi] += __shfl_xor_sync(0xffffffffu, ar[bi], off);
                az[bi] += __shfl_xor_sync(0xffffffffu, az[bi], off);
                an[bi] += __shfl_xor_sync(0xffffffffu, an[bi], off);
            }
        }
        if (ks == 0) {
            float br = bias_sm[jl * 3 + 0];
            float bz = bias_sm[jl * 3 + 1];
            float bn = bias_sm[jl * 3 + 2];
#pragma unroll
            for (int bi = 0; bi < 8; ++bi) {
                int b = bq * 8 + bi;
                float rr = fsigm(xr[bi] + ar[bi] + br);
                float zz = fsigm(xz[bi] + az[bi] + bz);
                float nn = ftanh(xn[bi] + rr * (an[bi] + bn));
                float hold = h_sm[b * HID + j];
                float hnew = (1.f - zz) * nn + zz * hold;
                g_h[(s + 1) & 1][b * HID + j]         = hnew;
                g_hs[(size_t)(s * BSZ + b) * HID + j] = hnew;
            }
        }
        if (s == SEQ - 1) break;

        // ---- grid barrier: contention-free distributed release ----
        __syncthreads();               // all CTA writes issued before arrive
        if (tid < 32) {
            unsigned old = 0;
            if (tid == 0) {
                asm volatile("atom.add.acq_rel.gpu.global.u32 %0, [%1], 1;"
                             : "=r"(old) : "l"(&g_bar) : "memory");
            }
            old = __shfl_sync(0xffffffffu, old, 0);
            const unsigned target = 128u * (unsigned)(s + 1);
            if (old == target - 1u) {    // last arriver: release everyone
#pragma unroll
                for (int i = 0; i < 4; ++i) {
                    unsigned idx = ((unsigned)tid * 4u + i) * 32u;
                    asm volatile("st.release.gpu.global.u32 [%0], %1;"
                                 :: "l"(&g_flag[idx]), "r"((unsigned)(s + 1))
                                 : "memory");
                }
            }
            if (tid == 0) {
                unsigned v;
                do {
                    asm volatile("ld.acquire.gpu.global.u32 %0, [%1];"
                                 : "=r"(v) : "l"(&g_flag[blockIdx.x * 32])
                                 : "memory");
                } while (v < (unsigned)(s + 1));
            }
        }
        __syncthreads();
    }
}

// ---------------- launch ----------------
extern "C" void kernel_launch(void* const* d_in, const int* in_sizes, int n_in,
                              void* d_out, int out_size) {
    const float* hidden    = (const float*)d_in[0];
    const void*  targets   = (const void*)d_in[1];
    const float* embedding = (const float*)d_in[2];
    const float* W_ih      = (const float*)d_in[3];
    const float* W_hh      = (const float*)d_in[4];
    const float* b_ih      = (const float*)d_in[5];
    const float* b_hh      = (const float*)d_in[6];
    const float* W_out     = (const float*)d_in[7];
    const float* b_out     = (const float*)d_in[8];
    const int*   init_tok  = (const int*)d_in[9];
    float*       out       = (float*)d_out;

    cudaFuncSetAttribute(recur_kernel,
                         cudaFuncAttributeMaxDynamicSharedMemorySize, 92160);

    init_kernel<<<16, 256>>>(targets, init_tok, hidden);

    // x_gates: [4096 x 1536 x 512], A gathered from embedding
    gemm_tf32<0><<<dim3(NGATE / 128, NTOK / 128), 256>>>(
        embedding, W_ih, b_ih, nullptr);

    // sequential GRU scan (persistent, 128 co-resident CTAs)
    recur_kernel<<<128, 256, 92160>>>(W_hh, b_hh);

    // logits: [4096 x 32000 x 512]
    gemm_tf32<1><<<dim3(VOC / 128, NTOK / 128), 256>>>(
        nullptr, W_out, b_out, out);
}